// round 13
// baseline (speedup 1.0000x reference)
#include <cuda_runtime.h>
#include <cuda_fp16.h>

#define BTOT     65536
#define ROWS_CTA 64
#define NCTA     (BTOT / ROWS_CTA)   // 1024
#define NTH      256                 // 8 warps = 2 quads x 32 rows
#define L_LAYERS 6
#define KT       7                   // k16 tiles: [0..49 in][50..99 h][100 bias][101..111 pad]
#define ASTR     240                 // conflict-free stride (60r mod 32 distinct)
#define NB       208                 // padded gate columns (13 blocks of 16)

#define B_BYTES  (NB * ASTR)              // 49920
#define A_OFF    B_BYTES
#define APAIR    (32 * ASTR)              // 7680
#define FCW_OFF  (A_OFF + 2 * APAIR)      // 65280
#define SMEM_BYTES 65536

#define NPBLK    (BTOT / 32)              // 2048 32-row blocks
#define YSTRIDE  1664                     // u16 per (t, block): 13 j * 128

typedef unsigned u32;
typedef unsigned short u16;

__device__ __align__(16) char g_wB[L_LAYERS * B_BYTES];     // fp16 weights+bias, 240B rows
__device__ u16                g_ys[3ull * NPBLK * YSTRIDE]; // coalesced [t][blk][j][row][q]

static __device__ __forceinline__ u32 smem_u32(const void* p) {
    u32 a;
    asm("{ .reg .u64 t; cvta.to.shared.u64 t, %1; cvt.u32.u64 %0, t; }" : "=r"(a) : "l"(p));
    return a;
}
static __device__ __forceinline__ void ldsm4(u32 addr, u32* r) {
    asm volatile("ldmatrix.sync.aligned.m8n8.x4.shared.b16 {%0,%1,%2,%3}, [%4];"
                 : "=r"(r[0]), "=r"(r[1]), "=r"(r[2]), "=r"(r[3]) : "r"(addr));
}
static __device__ __forceinline__ void mma4(float* c, const u32* a, u32 b0, u32 b1) {
    asm("mma.sync.aligned.m16n8k16.row.col.f32.f16.f16.f32 "
        "{%0,%1,%2,%3},{%4,%5,%6,%7},{%8,%9},{%0,%1,%2,%3};"
        : "+f"(c[0]), "+f"(c[1]), "+f"(c[2]), "+f"(c[3])
        : "r"(a[0]), "r"(a[1]), "r"(a[2]), "r"(a[3]), "r"(b0), "r"(b1));
}
static __device__ __forceinline__ float tanha(float x) {
    float r; asm("tanh.approx.f32 %0, %1;" : "=f"(r) : "f"(x)); return r;
}
#define BARP(id) asm volatile("bar.sync %0, 128;" :: "r"(id) : "memory")

// MUFU.TANH LSTM cell: 5 MUFU + 7 fma/mul
static __device__ __forceinline__ float lstm_cell(float gi, float gf, float gg, float go,
                                                  float& cst) {
    float i = __fmaf_rn(0.5f, tanha(0.5f * gi), 0.5f);
    float f = __fmaf_rn(0.5f, tanha(0.5f * gf), 0.5f);
    float o = __fmaf_rn(0.5f, tanha(0.5f * go), 0.5f);
    float g = tanha(gg);
    float cn = __fmaf_rn(f, cst, i * g);
    cst = cn;
    return o * tanha(cn);
}

// ---------------- prep: weights+bias -> fp16, shfl-free gate layout, 240B rows ----------------
__global__ void prep_kernel(const float* __restrict__ w_ih0, const float* __restrict__ w_ih,
                            const float* __restrict__ w_hh,  const float* __restrict__ b_ih,
                            const float* __restrict__ b_hh) {
    int idx = blockIdx.x * 256 + threadIdx.x;
    if (idx >= L_LAYERS * NB * 120) return;
    int k = idx % 120;
    int n = (idx / 120) % NB;
    int l = idx / (120 * NB);
    int u = 4 * (n >> 4) + ((n & 7) >> 1);
    int g = (n & 1) + 2 * ((n >> 3) & 1);
    float wv = 0.0f;
    if (u < 50) {
        int rt = g * 50 + u;
        if (k < 50)        wv = (l == 0) ? (k < 3 ? w_ih0[rt * 3 + k] : 0.0f)
                                         : w_ih[((size_t)(l - 1) * 200 + rt) * 50 + k];
        else if (k < 100)  wv = w_hh[((size_t)l * 200 + rt) * 50 + (k - 50)];
        else if (k == 100) wv = b_ih[l * 200 + rt] + b_hh[l * 200 + rt];
    }
    __half* base = (__half*)(g_wB + (size_t)l * B_BYTES);
    base[(size_t)n * 120 + k] = __float2half_rn(wv);
}

// one n16 tile: 7 ldsm + 28 mma + 4 cells; h -> A(smem) + coalesced ys(gmem)
// J may be runtime; CC is compile-time cr slot; FULL=1 -> unguarded h-column store
#define J_TILE(J, CC, FULL)                                                    \
  {                                                                            \
    float acc[16] = {0.f,0.f,0.f,0.f,0.f,0.f,0.f,0.f,                          \
                     0.f,0.f,0.f,0.f,0.f,0.f,0.f,0.f};                         \
    const u32 tb = bB4 + (u32)(J) * (16 * ASTR);                               \
    _Pragma("unroll")                                                          \
    for (int kt = 0; kt < KT; ++kt) {                                          \
        u32 bh[4];                                                             \
        ldsm4(tb + kt * 32, bh);                                               \
        mma4(acc + 0,  afr[0][kt], bh[0], bh[1]);                              \
        mma4(acc + 4,  afr[0][kt], bh[2], bh[3]);                              \
        mma4(acc + 8,  afr[1][kt], bh[0], bh[1]);                              \
        mma4(acc + 12, afr[1][kt], bh[2], bh[3]);                              \
    }                                                                          \
    const int u_ = 4 * (J) + q;                                                \
    _Pragma("unroll")                                                          \
    for (int mt = 0; mt < 2; ++mt)                                             \
      _Pragma("unroll")                                                        \
      for (int h8 = 0; h8 < 2; ++h8) {                                         \
        float hv = lstm_cell(acc[mt*8 + h8*2 + 0], acc[mt*8 + h8*2 + 1],       \
                             acc[mt*8 + 4 + h8*2 + 0], acc[mt*8 + 4 + h8*2+1], \
                             cr[(CC)*4 + mt*2 + h8]);                          \
        int row_ = r4 + 8*h8 + 16*mt;                                          \
        __half hh_ = __float2half_rn(hv);                                      \
        ysW[(J)*128 + row_*4 + q] = __half_as_ushort(hh_);                     \
        if ((FULL) || q < 2)                                                   \
            *(__half*)(Aq + row_*ASTR + (50 + u_)*2) = hh_;                    \
      }                                                                        \
  }

// ---------------- main ----------------
__global__ void __launch_bounds__(NTH, 2) lstm_hmma_kernel(
    const float* __restrict__ x,    const float* __restrict__ h0,
    const float* __restrict__ c0,   const float* __restrict__ fc_w,
    const float* __restrict__ fc_b, float* __restrict__ out)
{
    extern __shared__ char smem[];
    const u32 sbase = smem_u32(smem);
    const int tid = threadIdx.x, lane = tid & 31, w = tid >> 5;
    const int quad = w & 1, sq = w >> 1;          // quad interleaved across SMSPs
    const int q = lane & 3, r4 = lane >> 2;
    const int boff = blockIdx.x * ROWS_CTA;
    const int prb = boff + quad * 32;
    const int gpair = (blockIdx.x << 1) + quad;
    const int barid = 1 + quad;
    const int heavy = quad ? (sq == 3) : (sq == 0);   // rotate heavy warp per quad
    const int jb = 3 * sq;
    float* fcw_s = (float*)(smem + FCW_OFF);
    char* Aq = smem + A_OFF + quad * APAIR;
    char* Ar = Aq + lane * ASTR;

    for (int i = tid; i < (2 * APAIR) / 16; i += NTH)
        ((float4*)(smem + A_OFF))[i] = make_float4(0.f, 0.f, 0.f, 0.f);
    if (tid < 50) fcw_s[tid] = fc_w[tid];
    __syncthreads();
    if (sq == 0)
        *(__half*)(Ar + 200) = __float2half(1.0f);     // bias col k=100

    const u32 aB  = sbase + A_OFF + quad * APAIR + (lane & 15) * ASTR + (lane >> 4) * 16;
    const u32 bB4 = sbase + (lane & 7) * ASTR + ((lane >> 3) & 1) * 16
                          + ((lane >> 4) & 1) * (8 * ASTR);

    float cr[16];
    u32 afr[2][KT][4];

    #pragma unroll 1
    for (int l = 0; l < L_LAYERS; ++l) {
        __syncthreads();
        const float4* ws = (const float4*)(g_wB + (size_t)l * B_BYTES);
        for (int i = tid; i < B_BYTES / 16; i += NTH) ((float4*)smem)[i] = __ldg(ws + i);
        __syncthreads();

        // h0 -> A cols 50..99 (row = lane, cols strided by sq)
        {
            const float2* hp = (const float2*)(h0 + ((size_t)l * BTOT + prb + lane) * 50);
            for (int ci = sq; ci < 25; ci += 4) {
                float2 v = hp[ci];
                *(__half2*)(Ar + 100 + 4 * ci) =
                    __halves2half2(__float2half_rn(v.x), __float2half_rn(v.y));
            }
        }
        // c0 -> regs (16 per thread; own j-tiles only)
        {
            const float* cp = c0 + ((size_t)l * BTOT + prb) * 50;
            #pragma unroll
            for (int cc = 0; cc < 3; ++cc) {
                int u = 4 * (jb + cc) + q;
                #pragma unroll
                for (int mt = 0; mt < 2; ++mt)
                    #pragma unroll
                    for (int h8 = 0; h8 < 2; ++h8) {
                        int row = r4 + 8 * h8 + 16 * mt;
                        cr[cc * 4 + mt * 2 + h8] = (u < 50) ? cp[(size_t)row * 50 + u] : 0.f;
                    }
            }
            int u12 = 48 + q;
            #pragma unroll
            for (int mt = 0; mt < 2; ++mt)
                #pragma unroll
                for (int h8 = 0; h8 < 2; ++h8) {
                    int row = r4 + 8 * h8 + 16 * mt;
                    cr[12 + mt * 2 + h8] =
                        (heavy && u12 < 50) ? cp[(size_t)row * 50 + u12] : 0.f;
                }
        }

        #pragma unroll 1
        for (int t = 0; t < 3; ++t) {
            u16* ysW = g_ys + ((size_t)t * NPBLK + gpair) * YSTRIDE;

            // stage A input cols 0..49 (coalesced uint2 from own j-blocks)
            if (l == 0) {
                if (sq == 0) {
                    const float* xp = x + (size_t)(prb + lane) * 9 + t;
                    *(__half2*)(Ar) = __halves2half2(__float2half_rn(xp[0]),
                                                     __float2half_rn(xp[3]));
                    *(__half*)(Ar + 4) = __float2half_rn(xp[6]);
                }
            } else {
                #pragma unroll
                for (int cc = 0; cc < 3; ++cc) {
                    int j = jb + cc;
                    *(uint2*)(Ar + 8 * j) = *(const uint2*)(ysW + j * 128 + lane * 4);
                }
                if (heavy)
                    *(u32*)(Ar + 96) = *(const u32*)(ysW + 12 * 128 + lane * 4);
            }
            BARP(barid);                    // staging + quad's prev h-stores visible

            #pragma unroll
            for (int mt = 0; mt < 2; ++mt)
                #pragma unroll
                for (int kt = 0; kt < KT; ++kt)
                    ldsm4(aB + mt * (16 * ASTR) + kt * 32, afr[mt][kt]);
            BARP(barid);                    // A fully consumed; h-stores now safe

            J_TILE(jb,     0, 1)
            J_TILE(jb + 1, 1, 1)
            J_TILE(jb + 2, 2, 1)
            if (heavy) { J_TILE(12, 3, 0) }
        }
    }

    // FC from final h (fp16, in A cols 50..99)
    __syncthreads();
    if (tid < ROWS_CTA) {
        int pr = tid >> 5, rr = tid & 31;
        const __half2* hh = (const __half2*)(smem + A_OFF + pr * APAIR + rr * ASTR + 100);
        float s = 0.f;
        #pragma unroll
        for (int i = 0; i < 25; ++i) {
            float2 hv = __half22float2(hh[i]);
            s = __fmaf_rn(hv.x, fcw_s[2 * i], s);
            s = __fmaf_rn(hv.y, fcw_s[2 * i + 1], s);
        }
        out[boff + tid] = s + fc_b[0];
    }
}

extern "C" void kernel_launch(void* const* d_in, const int* in_sizes, int n_in,
                              void* d_out, int out_size) {
    const float* x     = (const float*)d_in[0];
    const float* h0    = (const float*)d_in[1];
    const float* c0    = (const float*)d_in[2];
    const float* w_ih0 = (const float*)d_in[3];
    const float* w_ih  = (const float*)d_in[4];
    const float* w_hh  = (const float*)d_in[5];
    const float* b_ih  = (const float*)d_in[6];
    const float* b_hh  = (const float*)d_in[7];
    const float* fc_w  = (const float*)d_in[8];
    const float* fc_b  = (const float*)d_in[9];
    float* out = (float*)d_out;

    prep_kernel<<<(L_LAYERS * NB * 120 + 255) / 256, 256>>>(w_ih0, w_ih, w_hh, b_ih, b_hh);

    static int once = 0;
    if (!once) {
        cudaFuncSetAttribute(lstm_hmma_kernel,
                             cudaFuncAttributeMaxDynamicSharedMemorySize, SMEM_BYTES);
        once = 1;
    }
    lstm_hmma_kernel<<<NCTA, NTH, SMEM_BYTES>>>(x, h0, c0, fc_w, fc_b, out);
}

// round 14
// speedup vs baseline: 1.2813x; 1.2813x over previous
#include <cuda_runtime.h>
#include <cuda_fp16.h>

#define BTOT     65536
#define ROWS_CTA 128
#define NCTA     (BTOT / ROWS_CTA)   // 512
#define NTH      256                 // 8 warps = 4 pairs x 32 rows
#define NPAIR    4
#define L_LAYERS 6
#define KT       7                   // layers>=1: [x 0..49][h 50..99][bias 100][pad]
#define KT0      4                   // layer 0:   [x 0..2][pad][h 4..53][bias 54][pad..63]
#define ASTR     240                 // conflict-free stride (60r mod 32 distinct)
#define NB       208                 // padded gate columns (13 blocks of 16)

#define B_BYTES  (NB * ASTR)              // 49920
#define A_OFF    B_BYTES
#define APAIR    (32 * ASTR)              // 7680
#define FCW_OFF  (A_OFF + NPAIR * APAIR)  // 80640
#define SMEM_BYTES 80896

#define NPBLK    (BTOT / 32)              // 2048 pair-blocks
#define YSTRIDE  1664                     // u16 per (t, pair-block): 13 j * 128

typedef unsigned u32;
typedef unsigned short u16;

__device__ __align__(16) char g_wB[L_LAYERS * B_BYTES];     // fp16 weights+bias, 240B rows
__device__ u16                g_ys[3ull * NPBLK * YSTRIDE]; // coalesced [t][blk][j][row][q]

static __device__ __forceinline__ u32 smem_u32(const void* p) {
    u32 a;
    asm("{ .reg .u64 t; cvta.to.shared.u64 t, %1; cvt.u32.u64 %0, t; }" : "=r"(a) : "l"(p));
    return a;
}
static __device__ __forceinline__ void ldsm4(u32 addr, u32* r) {
    asm volatile("ldmatrix.sync.aligned.m8n8.x4.shared.b16 {%0,%1,%2,%3}, [%4];"
                 : "=r"(r[0]), "=r"(r[1]), "=r"(r[2]), "=r"(r[3]) : "r"(addr));
}
static __device__ __forceinline__ void mma4(float* c, const u32* a, u32 b0, u32 b1) {
    asm("mma.sync.aligned.m16n8k16.row.col.f32.f16.f16.f32 "
        "{%0,%1,%2,%3},{%4,%5,%6,%7},{%8,%9},{%0,%1,%2,%3};"
        : "+f"(c[0]), "+f"(c[1]), "+f"(c[2]), "+f"(c[3])
        : "r"(a[0]), "r"(a[1]), "r"(a[2]), "r"(a[3]), "r"(b0), "r"(b1));
}
static __device__ __forceinline__ float tanha(float x) {
    float r; asm("tanh.approx.f32 %0, %1;" : "=f"(r) : "f"(x)); return r;
}
#define BARP(id) asm volatile("bar.sync %0, 64;" :: "r"(id) : "memory")

// MUFU.TANH LSTM cell: 5 MUFU + 7 fma/mul
static __device__ __forceinline__ float lstm_cell(float gi, float gf, float gg, float go,
                                                  float& cst) {
    float i = __fmaf_rn(0.5f, tanha(0.5f * gi), 0.5f);
    float f = __fmaf_rn(0.5f, tanha(0.5f * gf), 0.5f);
    float o = __fmaf_rn(0.5f, tanha(0.5f * go), 0.5f);
    float g = tanha(gg);
    float cn = __fmaf_rn(f, cst, i * g);
    cst = cn;
    return o * tanha(cn);
}

// ---------------- prep: weights+bias -> fp16, shfl-free gate layout ----------------
// layers>=1: k = [x 0..49][h 50..99][bias 100]; layer 0 compact: [x 0..2][h 4..53][bias 54]
__global__ void prep_kernel(const float* __restrict__ w_ih0, const float* __restrict__ w_ih,
                            const float* __restrict__ w_hh,  const float* __restrict__ b_ih,
                            const float* __restrict__ b_hh) {
    int idx = blockIdx.x * 256 + threadIdx.x;
    if (idx >= L_LAYERS * NB * 120) return;
    int k = idx % 120;
    int n = (idx / 120) % NB;
    int l = idx / (120 * NB);
    int u = 4 * (n >> 4) + ((n & 7) >> 1);
    int g = (n & 1) + 2 * ((n >> 3) & 1);
    float wv = 0.0f;
    if (u < 50) {
        int rt = g * 50 + u;
        if (l == 0) {
            if (k < 3)                  wv = w_ih0[rt * 3 + k];
            else if (k >= 4 && k < 54)  wv = w_hh[(size_t)rt * 50 + (k - 4)];
            else if (k == 54)           wv = b_ih[rt] + b_hh[rt];
        } else {
            if (k < 50)        wv = w_ih[((size_t)(l - 1) * 200 + rt) * 50 + k];
            else if (k < 100)  wv = w_hh[((size_t)l * 200 + rt) * 50 + (k - 50)];
            else if (k == 100) wv = b_ih[l * 200 + rt] + b_hh[l * 200 + rt];
        }
    }
    __half* base = (__half*)(g_wB + (size_t)l * B_BYTES);
    base[(size_t)n * 120 + k] = __float2half_rn(wv);
}

// one n16 tile: KTN ldsm + 4*KTN mma + 4 cells; h -> A(smem, byte base HB) + coalesced ys
#define J_TILE(J, CC, FULL, KTN, HB)                                           \
  {                                                                            \
    float acc[16] = {0.f,0.f,0.f,0.f,0.f,0.f,0.f,0.f,                          \
                     0.f,0.f,0.f,0.f,0.f,0.f,0.f,0.f};                         \
    const u32 tb = bB4 + (J) * (16 * ASTR);                                    \
    _Pragma("unroll")                                                          \
    for (int kt = 0; kt < (KTN); ++kt) {                                       \
        u32 bh[4];                                                             \
        ldsm4(tb + kt * 32, bh);                                               \
        mma4(acc + 0,  afr[0][kt], bh[0], bh[1]);                              \
        mma4(acc + 4,  afr[0][kt], bh[2], bh[3]);                              \
        mma4(acc + 8,  afr[1][kt], bh[0], bh[1]);                              \
        mma4(acc + 12, afr[1][kt], bh[2], bh[3]);                              \
    }                                                                          \
    const int u_ = 4 * (J) + q;                                                \
    _Pragma("unroll")                                                          \
    for (int mt = 0; mt < 2; ++mt)                                             \
      _Pragma("unroll")                                                        \
      for (int h8 = 0; h8 < 2; ++h8) {                                         \
        float hv = lstm_cell(acc[mt*8 + h8*2 + 0], acc[mt*8 + h8*2 + 1],       \
                             acc[mt*8 + 4 + h8*2 + 0], acc[mt*8 + 4 + h8*2+1], \
                             cr[(CC)*4 + mt*2 + h8]);                          \
        int row_ = r4 + 8*h8 + 16*mt;                                          \
        __half hh_ = __float2half_rn(hv);                                      \
        ysW[(J)*128 + row_*4 + q] = __half_as_ushort(hh_);                     \
        if ((FULL) || q < 2)                                                   \
            *(__half*)(Apair + row_*ASTR + (HB) + u_*2) = hh_;                 \
      }                                                                        \
  }

#define STEP_TILES(KTN, HB)                                                    \
    if (sub == 0) {                                                            \
        J_TILE(0, 0, 1, KTN, HB) J_TILE(1, 1, 1, KTN, HB)                      \
        J_TILE(2, 2, 1, KTN, HB) J_TILE(3, 3, 1, KTN, HB)                      \
        J_TILE(4, 4, 1, KTN, HB) J_TILE(5, 5, 1, KTN, HB)                      \
        J_TILE(6, 6, 1, KTN, HB)                                               \
    } else {                                                                   \
        J_TILE(7, 0, 1, KTN, HB) J_TILE(8, 1, 1, KTN, HB)                      \
        J_TILE(9, 2, 1, KTN, HB) J_TILE(10, 3, 1, KTN, HB)                     \
        J_TILE(11, 4, 1, KTN, HB) J_TILE(12, 5, 0, KTN, HB)                    \
    }

// ---------------- main ----------------
__global__ void __launch_bounds__(NTH, 2) lstm_hmma_kernel(
    const float* __restrict__ x,    const float* __restrict__ h0,
    const float* __restrict__ c0,   const float* __restrict__ fc_w,
    const float* __restrict__ fc_b, float* __restrict__ out)
{
    extern __shared__ char smem[];
    const u32 sbase = smem_u32(smem);
    const int tid = threadIdx.x, lane = tid & 31, w = tid >> 5;
    const int sub = w & 1, pid = w >> 1;
    const int q = lane & 3, r4 = lane >> 2;
    const int boff = blockIdx.x * ROWS_CTA;
    const int prb = boff + pid * 32;
    const int gpair = (blockIdx.x << 2) + pid;
    const int barid = 1 + pid;
    const int srow = lane;
    float* fcw_s = (float*)(smem + FCW_OFF);
    char* Apair = smem + A_OFF + pid * APAIR;
    char* Ar = Apair + srow * ASTR;

    for (int i = tid; i < (NPAIR * APAIR) / 16; i += NTH)
        ((float4*)(smem + A_OFF))[i] = make_float4(0.f, 0.f, 0.f, 0.f);
    if (tid < 50) fcw_s[tid] = fc_w[tid];
    __syncthreads();
    if (sub == 0) {
        *(__half*)(Ar + 108) = __float2half(1.0f);     // bias col 54 (layer-0 layout)
        *(__half*)(Ar + 200) = __float2half(1.0f);     // bias col 100 (layers >= 1)
    }

    const u32 aB  = sbase + A_OFF + pid * APAIR + (lane & 15) * ASTR + (lane >> 4) * 16;
    const u32 bB4 = sbase + (lane & 7) * ASTR + ((lane >> 3) & 1) * 16
                          + ((lane >> 4) & 1) * (8 * ASTR);

    float cr[28];
    u32 afr[2][KT][4];

    #pragma unroll 1
    for (int l = 0; l < L_LAYERS; ++l) {
        __syncthreads();
        const float4* ws = (const float4*)(g_wB + (size_t)l * B_BYTES);
        for (int i = tid; i < B_BYTES / 16; i += NTH) ((float4*)smem)[i] = __ldg(ws + i);
        __syncthreads();

        const int HB = (l == 0) ? 8 : 100;   // h-region byte base in A rows

        // h0 -> A h-region (fixed row per thread, col parity by sub)
        {
            const float2* hp = (const float2*)(h0 + ((size_t)l * BTOT + prb + srow) * 50);
            #pragma unroll
            for (int i = 0; i < 12; ++i) {
                int ci = 2 * i + sub;
                float2 v = hp[ci];
                *(__half2*)(Ar + HB + 4 * ci) =
                    __halves2half2(__float2half_rn(v.x), __float2half_rn(v.y));
            }
            if (sub == 0) {
                float2 v = hp[24];
                *(__half2*)(Ar + HB + 96) =
                    __halves2half2(__float2half_rn(v.x), __float2half_rn(v.y));
            }
        }
        // c0 -> regs (28 per thread; pad units get 0)
        {
            const float* cp = c0 + ((size_t)l * BTOT + prb) * 50;
            const int jbase = sub * 7;
            #pragma unroll
            for (int jj = 0; jj < 7; ++jj) {
                int u = 4 * (jbase + jj) + q;
                #pragma unroll
                for (int mt = 0; mt < 2; ++mt)
                    #pragma unroll
                    for (int h8 = 0; h8 < 2; ++h8) {
                        int row = r4 + 8 * h8 + 16 * mt;
                        cr[jj * 4 + mt * 2 + h8] = (u < 50) ? cp[(size_t)row * 50 + u] : 0.f;
                    }
            }
        }

        if (l == 0) {
            #pragma unroll 1
            for (int t = 0; t < 3; ++t) {
                u16* ysW = g_ys + ((size_t)t * NPBLK + gpair) * YSTRIDE;
                if (sub == 0) {                        // x -> cols 0..2
                    const float* xp = x + (size_t)(prb + srow) * 9 + t;
                    *(__half2*)(Ar) = __halves2half2(__float2half_rn(xp[0]),
                                                     __float2half_rn(xp[3]));
                    *(__half*)(Ar + 4) = __float2half_rn(xp[6]);
                }
                BARP(barid);
                #pragma unroll
                for (int mt = 0; mt < 2; ++mt)
                    #pragma unroll
                    for (int kt = 0; kt < KT0; ++kt)
                        ldsm4(aB + mt * (16 * ASTR) + kt * 32, afr[mt][kt]);
                BARP(barid);
                STEP_TILES(KT0, 8)
            }
        } else {
            #pragma unroll 1
            for (int t = 0; t < 3; ++t) {
                u16* ysW = g_ys + ((size_t)t * NPBLK + gpair) * YSTRIDE;
                // stage x-part = prev layer ys (coalesced uint2 from own j-blocks)
                if (sub == 0) {
                    #pragma unroll
                    for (int j = 0; j < 7; ++j)
                        *(uint2*)(Ar + 8 * j) = *(const uint2*)(ysW + j * 128 + srow * 4);
                } else {
                    #pragma unroll
                    for (int j = 7; j < 12; ++j)
                        *(uint2*)(Ar + 8 * j) = *(const uint2*)(ysW + j * 128 + srow * 4);
                    *(u32*)(Ar + 96) = *(const u32*)(ysW + 12 * 128 + srow * 4);
                }
                BARP(barid);
                #pragma unroll
                for (int mt = 0; mt < 2; ++mt)
                    #pragma unroll
                    for (int kt = 0; kt < KT; ++kt)
                        ldsm4(aB + mt * (16 * ASTR) + kt * 32, afr[mt][kt]);
                BARP(barid);
                STEP_TILES(KT, 100)
            }
        }
    }

    // FC from final h (fp16, in A cols 50..99 — layer 5 uses normal layout)
    __syncthreads();
    if (tid < 128) {
        int pr = tid >> 5, rr = tid & 31;
        const __half2* hh = (const __half2*)(smem + A_OFF + pr * APAIR + rr * ASTR + 100);
        float s = 0.f;
        #pragma unroll
        for (int i = 0; i < 25; ++i) {
            float2 hv = __half22float2(hh[i]);
            s = __fmaf_rn(hv.x, fcw_s[2 * i], s);
            s = __fmaf_rn(hv.y, fcw_s[2 * i + 1], s);
        }
        out[boff + tid] = s + fc_b[0];
    }
}

extern "C" void kernel_launch(void* const* d_in, const int* in_sizes, int n_in,
                              void* d_out, int out_size) {
    const float* x     = (const float*)d_in[0];
    const float* h0    = (const float*)d_in[1];
    const float* c0    = (const float*)d_in[2];
    const float* w_ih0 = (const float*)d_in[3];
    const float* w_ih  = (const float*)d_in[4];
    const float* w_hh  = (const float*)d_in[5];
    const float* b_ih  = (const float*)d_in[6];
    const float* b_hh  = (const float*)d_in[7];
    const float* fc_w  = (const float*)d_in[8];
    const float* fc_b  = (const float*)d_in[9];
    float* out = (float*)d_out;

    prep_kernel<<<(L_LAYERS * NB * 120 + 255) / 256, 256>>>(w_ih0, w_ih, w_hh, b_ih, b_hh);

    static int once = 0;
    if (!once) {
        cudaFuncSetAttribute(lstm_hmma_kernel,
                             cudaFuncAttributeMaxDynamicSharedMemorySize, SMEM_BYTES);
        once = 1;
    }
    lstm_hmma_kernel<<<NCTA, NTH, SMEM_BYTES>>>(x, h0, c0, fc_w, fc_b, out);
}